// round 16
// baseline (speedup 1.0000x reference)
#include <cuda_runtime.h>
#include <cuda_bf16.h>
#include <cstdint>

#define DIM 256
#define BATCH 2
#define M_ROWS (BATCH * DIM * DIM)   // 131072
#define HID (4 * DIM)                // 1024
#define EPS_LN 1e-5f

// Scratch. GEMM operands in TILE-BLOCK layout: 16KB block = (128 rows x 64 k)
// = 4 kg-slabs of 4KB; slab = row*32B; within 32B: 8 bf16-pairs at permuted
// position pos(p)=((p&3)<<1)|(p>>2), p=(k>>1)&7.
__device__ __align__(256) __nv_bfloat16 g_Y[(size_t)M_ROWS * DIM];
__device__ __align__(256) __nv_bfloat16 g_H[(size_t)M_ROWS * HID];
__device__ __align__(256) __nv_bfloat16 g_W1[(size_t)HID * DIM];
__device__ __align__(256) __nv_bfloat16 g_W2[(size_t)DIM * HID];

// cross-phase handoff state (re-zeroed every launch by conv kernel)
__device__ int g_tileCnt[1024];
__device__ unsigned g_jobCtr;

// ---------------------------------------------------------------------------
// helpers
// ---------------------------------------------------------------------------
__device__ __forceinline__ uint32_t smem_u32(const void* p) {
    uint32_t a;
    asm("{ .reg .u64 t; cvta.to.shared.u64 t, %1; cvt.u32.u64 %0, t; }"
        : "=r"(a) : "l"(p));
    return a;
}
__device__ __forceinline__ void mbar_init(uint32_t a, uint32_t cnt) {
    asm volatile("mbarrier.init.shared.b64 [%0], %1;" :: "r"(a), "r"(cnt) : "memory");
}
__device__ __forceinline__ void mbar_expect(uint32_t a, uint32_t tx) {
    asm volatile("mbarrier.arrive.expect_tx.shared.b64 _, [%0], %1;"
                 :: "r"(a), "r"(tx) : "memory");
}
__device__ __forceinline__ void mbar_arrive(uint32_t a) {
    asm volatile("mbarrier.arrive.shared.b64 _, [%0];" :: "r"(a) : "memory");
}
__device__ __forceinline__ void mbar_wait(uint32_t a, uint32_t parity) {
    asm volatile(
        "{\n\t.reg .pred P;\n\t"
        "W_%=:\n\t"
        "mbarrier.try_wait.parity.shared.b64 P, [%0], %1, 0x989680;\n\t"
        "@!P bra W_%=;\n\t}"
        :: "r"(a), "r"(parity) : "memory");
}
__device__ __forceinline__ void cpbulk(uint32_t dst, const void* src,
                                       uint32_t bytes, uint32_t mbar) {
    asm volatile(
        "cp.async.bulk.shared::cluster.global.mbarrier::complete_tx::bytes "
        "[%0], [%1], %2, [%3];"
        :: "r"(dst), "l"(src), "r"(bytes), "r"(mbar) : "memory");
}
__device__ __forceinline__ void mma_bf16(float* c, uint32_t a0, uint32_t a1,
                                         uint32_t a2, uint32_t a3,
                                         uint32_t b0, uint32_t b1) {
    asm volatile(
        "mma.sync.aligned.m16n8k16.row.col.f32.bf16.bf16.f32 "
        "{%0,%1,%2,%3}, {%4,%5,%6,%7}, {%8,%9}, {%0,%1,%2,%3};"
        : "+f"(c[0]), "+f"(c[1]), "+f"(c[2]), "+f"(c[3])
        : "r"(a0), "r"(a1), "r"(a2), "r"(a3), "r"(b0), "r"(b1));
}
__device__ __forceinline__ float gelu_fast(float v) {
    float inner = 0.7978845608028654f * v * fmaf(0.044715f, v * v, 1.0f);
    float t;
    asm("tanh.approx.f32 %0, %1;" : "=f"(t) : "f"(inner));
    float hv = 0.5f * v;
    return fmaf(hv, t, hv);
}
__device__ __forceinline__ uint64_t pack2(float lo, float hi) {
    uint64_t d;
    asm("mov.b64 %0, {%1, %2};" : "=l"(d) : "f"(lo), "f"(hi));
    return d;
}
__device__ __forceinline__ void unpack2(uint64_t v, float& lo, float& hi) {
    asm("mov.b64 {%0, %1}, %2;" : "=f"(lo), "=f"(hi) : "l"(v));
}
__device__ __forceinline__ void fma2(uint64_t& d, uint64_t a, uint64_t b) {
    asm("fma.rn.f32x2 %0, %1, %2, %0;" : "+l"(d) : "l"(a), "l"(b));
}
__device__ __forceinline__ uint64_t add2(uint64_t a, uint64_t b) {
    uint64_t d;
    asm("add.rn.f32x2 %0, %1, %2;" : "=l"(d) : "l"(a), "l"(b));
    return d;
}

// ---------------------------------------------------------------------------
// Kernel 1: conv + LN (16-row blocks) + fused weight prep + flag zeroing.
// ---------------------------------------------------------------------------
__global__ __launch_bounds__(128) void conv_ln_prep_kernel(
    const float* __restrict__ x, const float* __restrict__ cw,
    const float* __restrict__ cb, const float* __restrict__ g,
    const float* __restrict__ bta, __nv_bfloat16* __restrict__ Y,
    const float* __restrict__ w1, const float* __restrict__ w2,
    __nv_bfloat16* __restrict__ W1, __nv_bfloat16* __restrict__ W2)
{
    const int tid = threadIdx.x;
    const int bz = blockIdx.z;

    if (bz == BATCH) {
        // zero handoff flags (first 9 blocks of y==0 row)
        if (blockIdx.y == 0 && blockIdx.x < 9) {
            const int idx = blockIdx.x * 128 + tid;
            if (idx < 1024) g_tileCnt[idx] = 0;
            if (idx == 1024) g_jobCtr = 0u;
        }
        // weight prep: 4096 blocks x 128 elems = |w1| + |w2|
        const int i = (blockIdx.x + blockIdx.y * 16) * 128 + tid;
        if (i < HID * DIM) {
            const int n = i / DIM, k = i - n * DIM;
            const int p = (k >> 1) & 7, pos = ((p & 3) << 1) | (p >> 2);
            const size_t byte = (size_t)(n >> 7) * 65536 + (size_t)(k >> 4) * 4096
                              + (size_t)(n & 127) * 32 + pos * 4 + (k & 1) * 2;
            *(__nv_bfloat16*)((char*)W1 + byte) = __float2bfloat16(w1[i]);
        } else {
            const int i2 = i - HID * DIM;
            const int n = i2 / HID, k = i2 - n * HID;
            const int p = (k >> 1) & 7, pos = ((p & 3) << 1) | (p >> 2);
            const size_t byte = (size_t)((n >> 7) * 16 + (k >> 6)) * 16384
                              + (size_t)((k >> 4) & 3) * 4096
                              + (size_t)(n & 127) * 32 + pos * 4 + (k & 1) * 2;
            *(__nv_bfloat16*)((char*)W2 + byte) = __float2bfloat16(w2[i2]);
        }
        return;
    }

    __shared__ float s[22 * 262];
    __shared__ float swts[49];
    __shared__ float red[2][16][4];

    const int h0 = blockIdx.x * 16;
    const int c = blockIdx.y, b = bz;
    const int w0 = tid * 2;
    const int lane = tid & 31, warp = tid >> 5;

    if (tid < 49) swts[tid] = cw[c * 49 + tid];

    const float* xp = x + ((size_t)(b * DIM + c)) * DIM * DIM;
#pragma unroll
    for (int rr = 0; rr < 6; rr++) {
        const int ro = warp + rr * 4;
        if (ro < 22) {
            const int hh = h0 - 3 + ro;
            const bool hok = (hh >= 0) && (hh < DIM);
            const float* xr = xp + (size_t)hh * DIM;
            float* sr = s + ro * 262;
#pragma unroll
            for (int cc = 0; cc < 9; cc++) {
                const int col = lane + cc * 32;
                if (cc < 8 || col < 262) {
                    const int ww = col - 3;
                    float v = 0.f;
                    if (hok && ww >= 0 && ww < DIM) v = __ldg(xr + ww);
                    sr[col] = v;
                }
            }
        }
    }
    __syncthreads();

    uint64_t wp[49];
#pragma unroll
    for (int i = 0; i < 49; i++) { float w = swts[i]; wp[i] = pack2(w, w); }

    const float cbc = cb[c];
    uint64_t acc[16];
#pragma unroll
    for (int r = 0; r < 16; r++) acc[r] = pack2(cbc, cbc);

#pragma unroll
    for (int ro = 0; ro < 22; ro++) {
        float2 p0 = *(const float2*)&s[ro * 262 + w0];
        float2 p1 = *(const float2*)&s[ro * 262 + w0 + 2];
        float2 p2 = *(const float2*)&s[ro * 262 + w0 + 4];
        float2 p3 = *(const float2*)&s[ro * 262 + w0 + 6];
        float v[8] = {p0.x, p0.y, p1.x, p1.y, p2.x, p2.y, p3.x, p3.y};
        uint64_t vp[7];
#pragma unroll
        for (int kw = 0; kw < 7; kw++) vp[kw] = pack2(v[kw], v[kw + 1]);
#pragma unroll
        for (int r = 0; r < 16; r++) {
            const int kh = ro - r;
            if (kh >= 0 && kh < 7) {
#pragma unroll
                for (int kw = 0; kw < 7; kw++)
                    fma2(acc[r], vp[kw], wp[kh * 7 + kw]);
            }
        }
    }

#pragma unroll
    for (int r = 0; r < 16; r++) {
        float a0, a1;
        unpack2(acc[r], a0, a1);
        float sv = a0 + a1;
        float sq = a0 * a0 + a1 * a1;
#pragma unroll
        for (int o = 16; o; o >>= 1) {
            sv += __shfl_xor_sync(0xffffffffu, sv, o);
            sq += __shfl_xor_sync(0xffffffffu, sq, o);
        }
        if (lane == 0) { red[0][r][warp] = sv; red[1][r][warp] = sq; }
    }
    __syncthreads();

    const float gv0 = g[w0], gv1 = g[w0 + 1];
    const float bv0 = bta[w0], bv1 = bta[w0 + 1];
    const int p = tid & 7, pos = ((p & 3) << 1) | (p >> 2);
    const int j = w0 >> 6, kgl = (w0 >> 4) & 3;
    const size_t mbase = (size_t)(b * DIM + c) * DIM;
#pragma unroll
    for (int r = 0; r < 16; r++) {
        float a0, a1;
        unpack2(acc[r], a0, a1);
        float S  = red[0][r][0] + red[0][r][1] + red[0][r][2] + red[0][r][3];
        float S2 = red[1][r][0] + red[1][r][1] + red[1][r][2] + red[1][r][3];
        float mu  = S * (1.f / 256.f);
        float var = S2 * (1.f / 256.f) - mu * mu;
        float inv = rsqrtf(var + EPS_LN);
        __nv_bfloat162 o;
        o.x = __float2bfloat16((a0 - mu) * inv * gv0 + bv0);
        o.y = __float2bfloat16((a1 - mu) * inv * gv1 + bv1);
        const size_t m = mbase + h0 + r;
        const size_t byte = (size_t)((m >> 7) * 4 + j) * 16384
                          + kgl * 4096 + (m & 127) * 32 + pos * 4;
        *(__nv_bfloat162*)((char*)Y + byte) = o;
    }
}

// ---------------------------------------------------------------------------
// FUSED persistent GEMM kernel. 296 CTAs (2/SM, one wave).
// Phase A: gemm1 (panel, gr): H = gelu(Y @ W1^T + b1); per-tile release
//          (fence + atomic counter, 8 producers per m-tile).
// Phase B: gemm2 jobs (tile, panel) pulled from atomic ticket, acquire-spin
//          on tile readiness; out = H @ W2^T + b2 + x (transposed residual).
// mbarriers: [0..2] G1 full, [3..5] G1 empty, [6] panel,
//            [7..9] G2 full, [10..12] G2 empty.
// ---------------------------------------------------------------------------
__global__ void __launch_bounds__(128, 2) gemm_fused(
    const __nv_bfloat16* __restrict__ Yg, const __nv_bfloat16* __restrict__ W1g,
    const float* __restrict__ b1, __nv_bfloat16* __restrict__ Hg,
    const __nv_bfloat16* __restrict__ W2g, const float* __restrict__ b2,
    const float* __restrict__ xres, float* __restrict__ out)
{
    constexpr int NGR = 37;
    extern __shared__ char smem[];
    __shared__ uint64_t mbar[13];
    __shared__ unsigned s_job;
    const uint32_t sb = smem_u32(smem);
    const uint32_t mb = smem_u32(mbar);

    const int tid = threadIdx.x;
    const int panel = blockIdx.x & 7;
    const int gr = blockIdx.x >> 3;
    const int t0 = (gr * 1024) / NGR, t1 = ((gr + 1) * 1024) / NGR;
    const int n0 = panel * 128;
    const int total = (t1 - t0) * 4;

    if (tid == 0) {
#pragma unroll
        for (int s = 0; s < 3; s++) {
            mbar_init(mb + 8u * s, 1);            // G1 full
            mbar_init(mb + 24u + 8u * s, 128);    // G1 empty
            mbar_init(mb + 56u + 8u * s, 1);      // G2 full
            mbar_init(mb + 80u + 8u * s, 128);    // G2 empty
        }
        mbar_init(mb + 48u, 1);                   // panel
    }
    __syncthreads();

    const int warp = tid >> 5, lane = tid & 31;
    const int m_w = (warp >> 1) * 64, n_w = (warp & 1) * 64;
    const int r = lane >> 2, tig = lane & 3;

    // ======================= PHASE A: GEMM1 =======================
    {
        const char* Yb = (const char*)Yg;
        if (tid == 0) {
            mbar_expect(mb + 48u, 65536u);
            cpbulk(sb, (const char*)W1g + (size_t)panel * 65536, 65536u, mb + 48u);
#pragma unroll
            for (int I = 0; I < 2; I++) {
                mbar_expect(mb + 8u * I, 16384u);
                cpbulk(sb + 65536u + 16384u * I,
                       Yb + (size_t)(t0 * 4 + I) * 16384, 16384u, mb + 8u * I);
            }
        }
        mbar_wait(mb + 48u, 0);

        const int aoff = 65536 + (m_w + r) * 32 + tig * 8;
        const int boff = (n_w + r) * 32 + tig * 8;

        uint2 bfb[2][8];
#define LOADB(buf, slab) do {                                                 \
    const char* bk_ = smem + boff + (slab) * 4096;                            \
    _Pragma("unroll")                                                         \
    for (int ni_ = 0; ni_ < 8; ni_++)                                         \
        bfb[buf][ni_] = *(const uint2*)(bk_ + ni_ * 256);                     \
} while (0)

        int L = 0;
#pragma unroll 1
        for (int t = t0; t < t1; t++) {
            float acc[4][8][4] = {};
            LOADB(0, 0);
#pragma unroll 1
            for (int j = 0; j < 4; j++, L++) {
                if (tid == 0) {
                    const int I = L + 2;
                    if (I < total) {
                        const int s = I % 3;
                        if (I >= 3) mbar_wait(mb + 24u + 8u * s, ((I / 3) & 1) ^ 1);
                        mbar_expect(mb + 8u * s, 16384u);
                        cpbulk(sb + 65536u + 16384u * (uint32_t)s,
                               Yb + (size_t)(t0 * 4 + I) * 16384, 16384u,
                               mb + 8u * s);
                    }
                }
                const int s = L % 3;
                mbar_wait(mb + 8u * s, (uint32_t)((L / 3) & 1));

                const char* sa = smem + aoff + s * 16384;
#pragma unroll
                for (int kg = 0; kg < 4; kg++) {
                    const int cur = kg & 1;
                    const int nslab = (j * 4 + kg + 1) & 15;
                    LOADB(cur ^ 1, nslab);
                    const char* sk = sa + kg * 4096;
#pragma unroll
                    for (int mi = 0; mi < 4; mi++) {
                        uint2 alo = *(const uint2*)(sk + mi * 512);
                        uint2 ahi = *(const uint2*)(sk + mi * 512 + 256);
#pragma unroll
                        for (int ni = 0; ni < 8; ni++)
                            mma_bf16(acc[mi][ni], alo.x, ahi.x, alo.y, ahi.y,
                                     bfb[cur][ni].x, bfb[cur][ni].y);
                    }
                }
                mbar_arrive(mb + 24u + 8u * s);
            }

            // epilogue -> H
            char* Cb = (char*)Hg;
#pragma unroll
            for (int q = 0; q < 4; q++) {
                const int ne = n0 + n_w + q * 16 + 2 * tig;
                const float be0 = __ldg(b1 + ne),     be1 = __ldg(b1 + ne + 1);
                const float bo0 = __ldg(b1 + ne + 8), bo1 = __ldg(b1 + ne + 9);
                const size_t base = (size_t)(t * 16 + (ne >> 6)) * 16384
                                  + (size_t)((ne >> 4) & 3) * 4096 + tig * 8;
#pragma unroll
                for (int mi = 0; mi < 4; mi++) {
                    const int rr = m_w + mi * 16 + r;
                    const float* ae = acc[mi][2 * q];
                    const float* ao = acc[mi][2 * q + 1];
                    __nv_bfloat162 e0 = __floats2bfloat162_rn(
                        gelu_fast(ae[0] + be0), gelu_fast(ae[1] + be1));
                    __nv_bfloat162 o0 = __floats2bfloat162_rn(
                        gelu_fast(ao[0] + bo0), gelu_fast(ao[1] + bo1));
                    __nv_bfloat162 e1 = __floats2bfloat162_rn(
                        gelu_fast(ae[2] + be0), gelu_fast(ae[3] + be1));
                    __nv_bfloat162 o1 = __floats2bfloat162_rn(
                        gelu_fast(ao[2] + bo0), gelu_fast(ao[3] + bo1));
                    uint2 lo = make_uint2(*(uint32_t*)&e0, *(uint32_t*)&o0);
                    uint2 hi = make_uint2(*(uint32_t*)&e1, *(uint32_t*)&o1);
                    *(uint2*)(Cb + base + (size_t)rr * 32)       = lo;
                    *(uint2*)(Cb + base + (size_t)(rr + 8) * 32) = hi;
                }
            }

            // release tile t: stores -> fence (all threads) -> barrier -> count
            __threadfence();
            __syncthreads();
            if (tid == 0) atomicAdd(&g_tileCnt[t], 1);
        }
#undef LOADB
    }

    // ======================= PHASE B: GEMM2 jobs =======================
    __syncthreads();
    {
        const char* Hb = (const char*)Hg;
        const char* Wb = (const char*)W2g;
        const int aoff2 = (m_w + r) * 32 + tig * 8;
        const int boff2 = 16384 + (n_w + r) * 32 + tig * 8;
        int Ig = 0;   // issue index (tid0 only)
        int Wg = 0;   // wait index (all threads)

#pragma unroll 1
        for (;;) {
            if (tid == 0) s_job = atomicAdd(&g_jobCtr, 1u);
            __syncthreads();
            const unsigned tk = s_job;
            __syncthreads();
            if (tk >= 2072u) break;
            const int i = (int)(tk / 74u), rem = (int)(tk % 74u);
            const int g2 = rem >> 1, pn = rem & 1;
            const int tt0 = (g2 * 1024) / NGR, tt1 = ((g2 + 1) * 1024) / NGR;
            if (tt0 + i >= tt1) continue;
            const int t = tt0 + i;
            const int pn0 = pn * 128;

            // acquire-spin until all 8 producers released tile t
            if (tid == 0) {
                int v;
                for (;;) {
                    asm volatile("ld.acquire.gpu.global.s32 %0, [%1];"
                                 : "=r"(v) : "l"(&g_tileCnt[t]) : "memory");
                    if (v >= 8) break;
                    __nanosleep(128);
                }
            }
            __syncthreads();

#define ISSUE2J(IDX) do {                                                     \
    const int s_ = Ig % 3;                                                    \
    if (Ig >= 3) mbar_wait(mb + 80u + 8u * s_, (uint32_t)(((Ig / 3) & 1) ^ 1));\
    mbar_expect(mb + 56u + 8u * s_, 32768u);                                  \
    cpbulk(sb + 32768u * (uint32_t)s_,                                        \
           Hb + (size_t)(t * 16 + (IDX)) * 16384, 16384u, mb + 56u + 8u * s_);\
    cpbulk(sb + 32768u * (uint32_t)s_ + 16384u,                               \
           Wb + (size_t)(pn * 16 + (IDX)) * 16384, 16384u, mb + 56u + 8u * s_);\
    Ig++;                                                                     \
} while (0)

            if (tid == 0) { ISSUE2J(0); ISSUE2J(1); }

            float acc[4][8][4] = {};
#pragma unroll 1
            for (int L2 = 0; L2 < 16; L2++) {
                if (tid == 0 && L2 + 2 < 16) ISSUE2J(L2 + 2);
                const int s = Wg % 3;
                mbar_wait(mb + 56u + 8u * s, (uint32_t)((Wg / 3) & 1));
                Wg++;

                const char* st = smem + (size_t)s * 32768;
                uint2 bfb[2][8];
#pragma unroll
                for (int ni = 0; ni < 8; ni++)
                    bfb[0][ni] = *(const uint2*)(st + boff2 + ni * 256);
#pragma unroll
                for (int kg = 0; kg < 4; kg++) {
                    const int cur = kg & 1;
                    if (kg < 3) {
                        const char* bk = st + boff2 + (kg + 1) * 4096;
#pragma unroll
                        for (int ni = 0; ni < 8; ni++)
                            bfb[cur ^ 1][ni] = *(const uint2*)(bk + ni * 256);
                    }
                    const char* sk = st + aoff2 + kg * 4096;
#pragma unroll
                    for (int mi = 0; mi < 4; mi++) {
                        uint2 alo = *(const uint2*)(sk + mi * 512);
                        uint2 ahi = *(const uint2*)(sk + mi * 512 + 256);
#pragma unroll
                        for (int ni = 0; ni < 8; ni++)
                            mma_bf16(acc[mi][ni], alo.x, ahi.x, alo.y, ahi.y,
                                     bfb[cur][ni].x, bfb[cur][ni].y);
                    }
                }
                mbar_arrive(mb + 80u + 8u * s);
            }
#undef ISSUE2J

            // epilogue: smem transpose + bias + residual (stages are drained)
            __syncthreads();
            float* tile = (float*)smem;
#pragma unroll
            for (int ni = 0; ni < 8; ni++) {
                const int n_l = n_w + ni * 8 + 2 * tig;
#pragma unroll
                for (int mi = 0; mi < 4; mi++) {
                    const int m_l = m_w + mi * 16 + r;
                    tile[n_l * 132 + m_l]           = acc[mi][ni][0];
                    tile[(n_l + 1) * 132 + m_l]     = acc[mi][ni][1];
                    tile[n_l * 132 + m_l + 8]       = acc[mi][ni][2];
                    tile[(n_l + 1) * 132 + m_l + 8] = acc[mi][ni][3];
                }
            }
            __syncthreads();
            const int m0 = t * 128;
            const int bb = m0 >> 16, cc = (m0 >> 8) & 255, h0 = m0 & 255;
#pragma unroll
            for (int itr = 0; itr < 32; itr++) {
                const int nl = warp + itr * 4;
                const float bj = __ldg(b2 + pn0 + nl);
                const uint64_t bjp = pack2(bj, bj);
                size_t base = ((size_t)bb << 24) + ((size_t)(pn0 + nl) << 16)
                            + ((size_t)cc << 8) + (size_t)h0 + (size_t)(lane * 4);
                float4 tv = *(float4*)&tile[nl * 132 + lane * 4];
                float4 xv = *(const float4*)&xres[base];
                uint64_t* tp = (uint64_t*)&tv;
                const uint64_t* xp = (const uint64_t*)&xv;
                tp[0] = add2(add2(tp[0], bjp), xp[0]);
                tp[1] = add2(add2(tp[1], bjp), xp[1]);
                *(float4*)&out[base] = tv;
            }
            __syncthreads();   // tile reads done before next job's bulks
        }
    }
}

// ---------------------------------------------------------------------------
extern "C" void kernel_launch(void* const* d_in, const int* in_sizes, int n_in,
                              void* d_out, int out_size)
{
    (void)in_sizes; (void)n_in; (void)out_size;
    const float* x   = (const float*)d_in[0];
    const float* cw  = (const float*)d_in[1];
    const float* cb  = (const float*)d_in[2];
    const float* g   = (const float*)d_in[3];
    const float* bta = (const float*)d_in[4];
    const float* w1  = (const float*)d_in[5];
    const float* b1  = (const float*)d_in[6];
    const float* w2  = (const float*)d_in[7];
    const float* b2  = (const float*)d_in[8];
    float* out = (float*)d_out;

    __nv_bfloat16 *Y, *H, *W1, *W2;
    cudaGetSymbolAddress((void**)&Y,  g_Y);
    cudaGetSymbolAddress((void**)&H,  g_H);
    cudaGetSymbolAddress((void**)&W1, g_W1);
    cudaGetSymbolAddress((void**)&W2, g_W2);

    const int SMEM_F = 114688;   // 64KB panel + 48KB stages (covers G2's 96KB)
    cudaFuncSetAttribute(gemm_fused,
                         cudaFuncAttributeMaxDynamicSharedMemorySize, SMEM_F);

    // 1) conv + LN -> Y, weight prep, flag zeroing
    conv_ln_prep_kernel<<<dim3(DIM / 16, DIM, BATCH + 1), 128>>>(
        x, cw, cb, g, bta, Y, w1, w2, W1, W2);

    // 2) fused persistent GEMM1 -> flags -> GEMM2 (+ residual) -> out
    gemm_fused<<<296, 128, SMEM_F>>>(Y, W1, b1, H, W2, b2, x, out);
}

// round 17
// speedup vs baseline: 1.0686x; 1.0686x over previous
#include <cuda_runtime.h>
#include <cuda_bf16.h>
#include <cstdint>

#define DIM 256
#define BATCH 2
#define M_ROWS (BATCH * DIM * DIM)   // 131072
#define HID (4 * DIM)                // 1024
#define EPS_LN 1e-5f

// Scratch. GEMM operands in TILE-BLOCK layout: 16KB block = (128 rows x 64 k)
// = 4 kg-slabs of 4KB; slab = row*32B; within 32B: 8 bf16-pairs at permuted
// position pos(p)=((p&3)<<1)|(p>>2), p=(k>>1)&7. Blocks are contiguous so a
// whole stage loads with ONE cp.async.bulk.
__device__ __align__(256) __nv_bfloat16 g_Y[(size_t)M_ROWS * DIM];
__device__ __align__(256) __nv_bfloat16 g_H[(size_t)M_ROWS * HID];
__device__ __align__(256) __nv_bfloat16 g_W1[(size_t)HID * DIM];
__device__ __align__(256) __nv_bfloat16 g_W2[(size_t)DIM * HID];

// ---------------------------------------------------------------------------
// helpers
// ---------------------------------------------------------------------------
__device__ __forceinline__ uint32_t smem_u32(const void* p) {
    uint32_t a;
    asm("{ .reg .u64 t; cvta.to.shared.u64 t, %1; cvt.u32.u64 %0, t; }"
        : "=r"(a) : "l"(p));
    return a;
}
__device__ __forceinline__ void cp16(uint32_t dst, const void* src) {
    asm volatile("cp.async.cg.shared.global [%0], [%1], 16;"
                 :: "r"(dst), "l"(src) : "memory");
}
__device__ __forceinline__ void cp_commit() {
    asm volatile("cp.async.commit_group;" ::: "memory");
}
template<int N> __device__ __forceinline__ void cp_wait() {
    asm volatile("cp.async.wait_group %0;" :: "n"(N) : "memory");
}
__device__ __forceinline__ void mbar_init(uint32_t a, uint32_t cnt) {
    asm volatile("mbarrier.init.shared.b64 [%0], %1;" :: "r"(a), "r"(cnt) : "memory");
}
__device__ __forceinline__ void mbar_expect(uint32_t a, uint32_t tx) {
    asm volatile("mbarrier.arrive.expect_tx.shared.b64 _, [%0], %1;"
                 :: "r"(a), "r"(tx) : "memory");
}
__device__ __forceinline__ void mbar_arrive(uint32_t a) {
    asm volatile("mbarrier.arrive.shared.b64 _, [%0];" :: "r"(a) : "memory");
}
__device__ __forceinline__ void mbar_wait(uint32_t a, uint32_t parity) {
    asm volatile(
        "{\n\t.reg .pred P;\n\t"
        "W_%=:\n\t"
        "mbarrier.try_wait.parity.shared.b64 P, [%0], %1, 0x989680;\n\t"
        "@!P bra W_%=;\n\t}"
        :: "r"(a), "r"(parity) : "memory");
}
__device__ __forceinline__ void cpbulk(uint32_t dst, const void* src,
                                       uint32_t bytes, uint32_t mbar) {
    asm volatile(
        "cp.async.bulk.shared::cluster.global.mbarrier::complete_tx::bytes "
        "[%0], [%1], %2, [%3];"
        :: "r"(dst), "l"(src), "r"(bytes), "r"(mbar) : "memory");
}
__device__ __forceinline__ void mma_bf16(float* c, uint32_t a0, uint32_t a1,
                                         uint32_t a2, uint32_t a3,
                                         uint32_t b0, uint32_t b1) {
    asm volatile(
        "mma.sync.aligned.m16n8k16.row.col.f32.bf16.bf16.f32 "
        "{%0,%1,%2,%3}, {%4,%5,%6,%7}, {%8,%9}, {%0,%1,%2,%3};"
        : "+f"(c[0]), "+f"(c[1]), "+f"(c[2]), "+f"(c[3])
        : "r"(a0), "r"(a1), "r"(a2), "r"(a3), "r"(b0), "r"(b1));
}
__device__ __forceinline__ float gelu_fast(float v) {
    float inner = 0.7978845608028654f * v * fmaf(0.044715f, v * v, 1.0f);
    float t;
    asm("tanh.approx.f32 %0, %1;" : "=f"(t) : "f"(inner));
    float hv = 0.5f * v;
    return fmaf(hv, t, hv);
}
__device__ __forceinline__ uint64_t pack2(float lo, float hi) {
    uint64_t d;
    asm("mov.b64 %0, {%1, %2};" : "=l"(d) : "f"(lo), "f"(hi));
    return d;
}
__device__ __forceinline__ void unpack2(uint64_t v, float& lo, float& hi) {
    asm("mov.b64 {%0, %1}, %2;" : "=f"(lo), "=f"(hi) : "l"(v));
}
__device__ __forceinline__ void fma2(uint64_t& d, uint64_t a, uint64_t b) {
    asm("fma.rn.f32x2 %0, %1, %2, %0;" : "+l"(d) : "l"(a), "l"(b));
}
__device__ __forceinline__ uint64_t add2(uint64_t a, uint64_t b) {
    uint64_t d;
    asm("add.rn.f32x2 %0, %1, %2;" : "=l"(d) : "l"(a), "l"(b));
    return d;
}

// ---------------------------------------------------------------------------
// Kernel 1: conv + LN (16-row blocks) + fused weight prep on z==BATCH slice.
// Fill via cp.async.cg (rows stored at smem col 4, pitch 272; halo zeroed).
// ---------------------------------------------------------------------------
#define CPITCH 272

__global__ __launch_bounds__(128) void conv_ln_prep_kernel(
    const float* __restrict__ x, const float* __restrict__ cw,
    const float* __restrict__ cb, const float* __restrict__ g,
    const float* __restrict__ bta, __nv_bfloat16* __restrict__ Y,
    const float* __restrict__ w1, const float* __restrict__ w2,
    __nv_bfloat16* __restrict__ W1, __nv_bfloat16* __restrict__ W2)
{
    const int tid = threadIdx.x;
    const int bz = blockIdx.z;

    if (bz == BATCH) {
        // weight prep: 4096 blocks x 128 elems = |w1| + |w2|
        const int i = (blockIdx.x + blockIdx.y * 16) * 128 + tid;
        if (i < HID * DIM) {
            const int n = i / DIM, k = i - n * DIM;
            const int p = (k >> 1) & 7, pos = ((p & 3) << 1) | (p >> 2);
            const size_t byte = (size_t)(n >> 7) * 65536 + (size_t)(k >> 4) * 4096
                              + (size_t)(n & 127) * 32 + pos * 4 + (k & 1) * 2;
            *(__nv_bfloat16*)((char*)W1 + byte) = __float2bfloat16(w1[i]);
        } else {
            const int i2 = i - HID * DIM;
            const int n = i2 / HID, k = i2 - n * HID;
            const int p = (k >> 1) & 7, pos = ((p & 3) << 1) | (p >> 2);
            const size_t byte = (size_t)((n >> 7) * 16 + (k >> 6)) * 16384
                              + (size_t)((k >> 4) & 3) * 4096
                              + (size_t)(n & 127) * 32 + pos * 4 + (k & 1) * 2;
            *(__nv_bfloat16*)((char*)W2 + byte) = __float2bfloat16(w2[i2]);
        }
        return;
    }

    __shared__ __align__(16) float s[22 * CPITCH];
    __shared__ float swts[49];
    __shared__ float red[2][16][4];

    const int h0 = blockIdx.x * 16;
    const int c = blockIdx.y, b = bz;
    const int w0 = tid * 2;
    const int lane = tid & 31, warp = tid >> 5;

    if (tid < 49) swts[tid] = cw[c * 49 + tid];

    // ---- fill: smem row ro holds x row hh at cols [4, 260); halo zeroed ----
    const float* xp = x + ((size_t)(b * DIM + c)) * DIM * DIM;
    const uint32_t su = smem_u32(s);
    const float4 z4 = make_float4(0.f, 0.f, 0.f, 0.f);
#pragma unroll
    for (int rr = 0; rr < 6; rr++) {
        const int ro = warp + rr * 4;
        if (ro < 22) {
            const int hh = h0 - 3 + ro;
            float* sr = s + ro * CPITCH;
            if (hh >= 0 && hh < DIM) {
                const char* src = (const char*)(xp + (size_t)hh * DIM);
                const uint32_t d0 = su + (uint32_t)(ro * CPITCH + 4) * 4u;
                cp16(d0 + (uint32_t)lane * 16u,        src + lane * 16);
                cp16(d0 + (uint32_t)(lane + 32) * 16u, src + (lane + 32) * 16);
                if (lane == 0)      *(float4*)(sr)       = z4;   // cols 0..3
                else if (lane == 1) *(float4*)(sr + 260) = z4;   // cols 260..263
            } else {
                // zero cols 0..263 (66 x 16B chunks)
                *(float4*)(sr + lane * 4)        = z4;
                *(float4*)(sr + (lane + 32) * 4) = z4;
                if (lane < 2) *(float4*)(sr + (lane + 64) * 4) = z4;
            }
        }
    }
    cp_commit();
    cp_wait<0>();
    __syncthreads();

    uint64_t wp[49];
#pragma unroll
    for (int i = 0; i < 49; i++) { float w = swts[i]; wp[i] = pack2(w, w); }

    const float cbc = cb[c];
    uint64_t acc[16];
#pragma unroll
    for (int r = 0; r < 16; r++) acc[r] = pack2(cbc, cbc);

#pragma unroll
    for (int ro = 0; ro < 22; ro++) {
        // f[0..9] = x[w0-4 .. w0+5] (smem col 4+ww; load base col w0)
        float2 q0 = *(const float2*)&s[ro * CPITCH + w0];
        float2 q1 = *(const float2*)&s[ro * CPITCH + w0 + 2];
        float2 q2 = *(const float2*)&s[ro * CPITCH + w0 + 4];
        float2 q3 = *(const float2*)&s[ro * CPITCH + w0 + 6];
        float2 q4 = *(const float2*)&s[ro * CPITCH + w0 + 8];
        float f[10] = {q0.x, q0.y, q1.x, q1.y, q2.x, q2.y,
                       q3.x, q3.y, q4.x, q4.y};
        uint64_t vp[7];
#pragma unroll
        for (int kw = 0; kw < 7; kw++) vp[kw] = pack2(f[kw + 1], f[kw + 2]);
#pragma unroll
        for (int r = 0; r < 16; r++) {
            const int kh = ro - r;
            if (kh >= 0 && kh < 7) {
#pragma unroll
                for (int kw = 0; kw < 7; kw++)
                    fma2(acc[r], vp[kw], wp[kh * 7 + kw]);
            }
        }
    }

#pragma unroll
    for (int r = 0; r < 16; r++) {
        float a0, a1;
        unpack2(acc[r], a0, a1);
        float sv = a0 + a1;
        float sq = a0 * a0 + a1 * a1;
#pragma unroll
        for (int o = 16; o; o >>= 1) {
            sv += __shfl_xor_sync(0xffffffffu, sv, o);
            sq += __shfl_xor_sync(0xffffffffu, sq, o);
        }
        if (lane == 0) { red[0][r][warp] = sv; red[1][r][warp] = sq; }
    }
    __syncthreads();

    const float gv0 = g[w0], gv1 = g[w0 + 1];
    const float bv0 = bta[w0], bv1 = bta[w0 + 1];
    const int p = tid & 7, pos = ((p & 3) << 1) | (p >> 2);
    const int j = w0 >> 6, kgl = (w0 >> 4) & 3;
    const size_t mbase = (size_t)(b * DIM + c) * DIM;
#pragma unroll
    for (int r = 0; r < 16; r++) {
        float a0, a1;
        unpack2(acc[r], a0, a1);
        float S  = red[0][r][0] + red[0][r][1] + red[0][r][2] + red[0][r][3];
        float S2 = red[1][r][0] + red[1][r][1] + red[1][r][2] + red[1][r][3];
        float mu  = S * (1.f / 256.f);
        float var = S2 * (1.f / 256.f) - mu * mu;
        float inv = rsqrtf(var + EPS_LN);
        __nv_bfloat162 o;
        o.x = __float2bfloat16((a0 - mu) * inv * gv0 + bv0);
        o.y = __float2bfloat16((a1 - mu) * inv * gv1 + bv1);
        const size_t m = mbase + h0 + r;
        const size_t byte = (size_t)((m >> 7) * 4 + j) * 16384
                          + kgl * 4096 + (m & 127) * 32 + pos * 4;
        *(__nv_bfloat162*)((char*)Y + byte) = o;
    }
}

// ---------------------------------------------------------------------------
// GEMM1 persistent (frozen, R15): H = gelu(Y @ W1^T + b1).
// ---------------------------------------------------------------------------
__global__ void __launch_bounds__(128, 2) gemm1_persist(
    const __nv_bfloat16* __restrict__ A, const __nv_bfloat16* __restrict__ Bm,
    const float* __restrict__ bias, __nv_bfloat16* __restrict__ C)
{
    constexpr int NGR = 37;
    extern __shared__ char smem[];          // [0,64K) panel, [64K,112K) stages
    __shared__ uint64_t mbar[7];            // full0..2, empty0..2, panel
    const uint32_t sb = smem_u32(smem);
    const uint32_t mb = smem_u32(mbar);

    const int tid = threadIdx.x;
    const int panel = blockIdx.x & 7;
    const int gr = blockIdx.x >> 3;
    const int t0 = (gr * 1024) / NGR, t1 = ((gr + 1) * 1024) / NGR;
    const int n0 = panel * 128;
    const int total = (t1 - t0) * 4;

    if (tid == 0) {
#pragma unroll
        for (int s = 0; s < 3; s++) {
            mbar_init(mb + 8u * s, 1);
            mbar_init(mb + 24u + 8u * s, 128);
        }
        mbar_init(mb + 48u, 1);
    }
    __syncthreads();

    const char* Yb = (const char*)A;
    if (tid == 0) {
        mbar_expect(mb + 48u, 65536u);
        cpbulk(sb, (const char*)Bm + (size_t)panel * 65536, 65536u, mb + 48u);
#pragma unroll
        for (int I = 0; I < 2; I++) {
            mbar_expect(mb + 8u * I, 16384u);
            cpbulk(sb + 65536u + 16384u * I,
                   Yb + (size_t)(t0 * 4 + I) * 16384, 16384u, mb + 8u * I);
        }
    }
    mbar_wait(mb + 48u, 0);

    const int warp = tid >> 5, lane = tid & 31;
    const int m_w = (warp >> 1) * 64, n_w = (warp & 1) * 64;
    const int r = lane >> 2, tig = lane & 3;
    const int aoff = 65536 + (m_w + r) * 32 + tig * 8;
    const int boff = (n_w + r) * 32 + tig * 8;

    uint2 bfb[2][8];
#define LOADB(buf, slab) do {                                                 \
    const char* bk_ = smem + boff + (slab) * 4096;                            \
    _Pragma("unroll")                                                         \
    for (int ni_ = 0; ni_ < 8; ni_++)                                         \
        bfb[buf][ni_] = *(const uint2*)(bk_ + ni_ * 256);                     \
} while (0)

    int L = 0;
#pragma unroll 1
    for (int t = t0; t < t1; t++) {
        float acc[4][8][4] = {};
        LOADB(0, 0);
#pragma unroll 1
        for (int j = 0; j < 4; j++, L++) {
            if (tid == 0) {
                const int I = L + 2;
                if (I < total) {
                    const int s = I % 3;
                    if (I >= 3) mbar_wait(mb + 24u + 8u * s, ((I / 3) & 1) ^ 1);
                    mbar_expect(mb + 8u * s, 16384u);
                    cpbulk(sb + 65536u + 16384u * (uint32_t)s,
                           Yb + (size_t)(t0 * 4 + I) * 16384, 16384u, mb + 8u * s);
                }
            }
            const int s = L % 3;
            mbar_wait(mb + 8u * s, (uint32_t)((L / 3) & 1));

            const char* sa = smem + aoff + s * 16384;
#pragma unroll
            for (int kg = 0; kg < 4; kg++) {
                const int cur = kg & 1;
                const int nslab = (j * 4 + kg + 1) & 15;
                LOADB(cur ^ 1, nslab);
                const char* sk = sa + kg * 4096;
#pragma unroll
                for (int mi = 0; mi < 4; mi++) {
                    uint2 alo = *(const uint2*)(sk + mi * 512);
                    uint2 ahi = *(const uint2*)(sk + mi * 512 + 256);
#pragma unroll
                    for (int ni = 0; ni < 8; ni++)
                        mma_bf16(acc[mi][ni], alo.x, ahi.x, alo.y, ahi.y,
                                 bfb[cur][ni].x, bfb[cur][ni].y);
                }
            }
            mbar_arrive(mb + 24u + 8u * s);
        }

        char* Cb = (char*)C;
#pragma unroll
        for (int q = 0; q < 4; q++) {
            const int ne = n0 + n_w + q * 16 + 2 * tig;
            const float be0 = __ldg(bias + ne),     be1 = __ldg(bias + ne + 1);
            const float bo0 = __ldg(bias + ne + 8), bo1 = __ldg(bias + ne + 9);
            const size_t base = (size_t)(t * 16 + (ne >> 6)) * 16384
                              + (size_t)((ne >> 4) & 3) * 4096 + tig * 8;
#pragma unroll
            for (int mi = 0; mi < 4; mi++) {
                const int rr = m_w + mi * 16 + r;
                const float* ae = acc[mi][2 * q];
                const float* ao = acc[mi][2 * q + 1];
                __nv_bfloat162 e0 = __floats2bfloat162_rn(
                    gelu_fast(ae[0] + be0), gelu_fast(ae[1] + be1));
                __nv_bfloat162 o0 = __floats2bfloat162_rn(
                    gelu_fast(ao[0] + bo0), gelu_fast(ao[1] + bo1));
                __nv_bfloat162 e1 = __floats2bfloat162_rn(
                    gelu_fast(ae[2] + be0), gelu_fast(ae[3] + be1));
                __nv_bfloat162 o1 = __floats2bfloat162_rn(
                    gelu_fast(ao[2] + bo0), gelu_fast(ao[3] + bo1));
                uint2 lo = make_uint2(*(uint32_t*)&e0, *(uint32_t*)&o0);
                uint2 hi = make_uint2(*(uint32_t*)&e1, *(uint32_t*)&o1);
                *(uint2*)(Cb + base + (size_t)rr * 32)       = lo;
                *(uint2*)(Cb + base + (size_t)(rr + 8) * 32) = hi;
            }
        }
    }
#undef LOADB
}

// ---------------------------------------------------------------------------
// GEMM2 (frozen, R15): out = H @ W2^T + b2 + x.
// ---------------------------------------------------------------------------
__global__ void __launch_bounds__(128, 2) gemm2_bf16(
    const __nv_bfloat16* __restrict__ A, const __nv_bfloat16* __restrict__ Bm,
    const float* __restrict__ bias, const float* __restrict__ xres,
    float* __restrict__ C)
{
    extern __shared__ char smem[];          // 3 x 32KB stages
    __shared__ uint64_t mbar[6];            // full0..2, empty0..2
    const uint32_t sb = smem_u32(smem);
    const uint32_t mb = smem_u32(mbar);

    const int tid = threadIdx.x;
    const int t = blockIdx.y;               // m-tile
    const int panel = blockIdx.x;           // 0..1
    const int m0 = t * 128, n0 = panel * 128;
    const char* Hb = (const char*)A;
    const char* Wb = (const char*)Bm;

    if (tid == 0) {
#pragma unroll
        for (int s = 0; s < 3; s++) {
            mbar_init(mb + 8u * s, 1);
            mbar_init(mb + 24u + 8u * s, 128);
        }
    }
    __syncthreads();

#define ISSUE2(I) do {                                                        \
    const int s_ = (I) % 3;                                                   \
    if ((I) >= 3) mbar_wait(mb + 24u + 8u * s_, (((I) / 3) & 1) ^ 1);         \
    mbar_expect(mb + 8u * s_, 32768u);                                        \
    cpbulk(sb + 32768u * (uint32_t)s_,                                        \
           Hb + (size_t)(t * 16 + (I)) * 16384, 16384u, mb + 8u * s_);        \
    cpbulk(sb + 32768u * (uint32_t)s_ + 16384u,                               \
           Wb + (size_t)(panel * 16 + (I)) * 16384, 16384u, mb + 8u * s_);    \
} while (0)

    if (tid == 0) { ISSUE2(0); ISSUE2(1); }

    const int warp = tid >> 5, lane = tid & 31;
    const int m_w = (warp >> 1) * 64, n_w = (warp & 1) * 64;
    const int r = lane >> 2, tig = lane & 3;
    const int aoff = (m_w + r) * 32 + tig * 8;
    const int boff = 16384 + (n_w + r) * 32 + tig * 8;

    float acc[4][8][4] = {};

#pragma unroll 1
    for (int L = 0; L < 16; L++) {
        if (tid == 0 && L + 2 < 16) ISSUE2(L + 2);
        const int s = L % 3;
        mbar_wait(mb + 8u * s, (uint32_t)((L / 3) & 1));

        const char* st = smem + (size_t)s * 32768;
        uint2 bfb[2][8];
#pragma unroll
        for (int ni = 0; ni < 8; ni++)
            bfb[0][ni] = *(const uint2*)(st + boff + ni * 256);
#pragma unroll
        for (int kg = 0; kg < 4; kg++) {
            const int cur = kg & 1;
            if (kg < 3) {
                const char* bk = st + boff + (kg + 1) * 4096;
#pragma unroll
                for (int ni = 0; ni < 8; ni++)
                    bfb[cur ^ 1][ni] = *(const uint2*)(bk + ni * 256);
            }
            const char* sk = st + aoff + kg * 4096;
#pragma unroll
            for (int mi = 0; mi < 4; mi++) {
                uint2 alo = *(const uint2*)(sk + mi * 512);
                uint2 ahi = *(const uint2*)(sk + mi * 512 + 256);
#pragma unroll
                for (int ni = 0; ni < 8; ni++)
                    mma_bf16(acc[mi][ni], alo.x, ahi.x, alo.y, ahi.y,
                             bfb[cur][ni].x, bfb[cur][ni].y);
            }
        }
        mbar_arrive(mb + 24u + 8u * s);
    }
#undef ISSUE2

    __syncthreads();
    float* tile = (float*)smem;
#pragma unroll
    for (int ni = 0; ni < 8; ni++) {
        const int n_l = n_w + ni * 8 + 2 * tig;
#pragma unroll
        for (int mi = 0; mi < 4; mi++) {
            const int m_l = m_w + mi * 16 + r;
            tile[n_l * 132 + m_l]           = acc[mi][ni][0];
            tile[(n_l + 1) * 132 + m_l]     = acc[mi][ni][1];
            tile[n_l * 132 + m_l + 8]       = acc[mi][ni][2];
            tile[(n_l + 1) * 132 + m_l + 8] = acc[mi][ni][3];
        }
    }
    __syncthreads();
    const int bb = m0 >> 16, cc = (m0 >> 8) & 255, h0 = m0 & 255;
#pragma unroll
    for (int itr = 0; itr < 32; itr++) {
        const int nl = warp + itr * 4;
        const float bj = __ldg(bias + n0 + nl);
        const uint64_t bjp = pack2(bj, bj);
        size_t base = ((size_t)bb << 24) + ((size_t)(n0 + nl) << 16)
                    + ((size_t)cc << 8) + (size_t)h0 + (size_t)(lane * 4);
        float4 tv = *(float4*)&tile[nl * 132 + lane * 4];
        float4 xv = *(const float4*)&xres[base];
        uint64_t* tp = (uint64_t*)&tv;
        const uint64_t* xp = (const uint64_t*)&xv;
        tp[0] = add2(add2(tp[0], bjp), xp[0]);
        tp[1] = add2(add2(tp[1], bjp), xp[1]);
        *(float4*)&C[base] = tv;
    }
}

// ---------------------------------------------------------------------------
extern "C" void kernel_launch(void* const* d_in, const int* in_sizes, int n_in,
                              void* d_out, int out_size)
{
    (void)in_sizes; (void)n_in; (void)out_size;
    const float* x   = (const float*)d_in[0];
    const float* cw  = (const float*)d_in[1];
    const float* cb  = (const float*)d_in[2];
    const float* g   = (const float*)d_in[3];
    const float* bta = (const float*)d_in[4];
    const float* w1  = (const float*)d_in[5];
    const float* b1  = (const float*)d_in[6];
    const float* w2  = (const float*)d_in[7];
    const float* b2  = (const float*)d_in[8];
    float* out = (float*)d_out;

    __nv_bfloat16 *Y, *H, *W1, *W2;
    cudaGetSymbolAddress((void**)&Y,  g_Y);
    cudaGetSymbolAddress((void**)&H,  g_H);
    cudaGetSymbolAddress((void**)&W1, g_W1);
    cudaGetSymbolAddress((void**)&W2, g_W2);

    const int SMEM_G1 = 114688;  // 64KB panel + 3 x 16KB A stages
    const int SMEM_G2 = 98304;   // 3 x 32KB stages (>= 67.6KB transpose tile)
    cudaFuncSetAttribute(gemm1_persist,
                         cudaFuncAttributeMaxDynamicSharedMemorySize, SMEM_G1);
    cudaFuncSetAttribute(gemm2_bf16,
                         cudaFuncAttributeMaxDynamicSharedMemorySize, SMEM_G2);

    // 1) conv + LN -> Y (16-row tiles, cp.async fill), + weight prep on z==2
    conv_ln_prep_kernel<<<dim3(DIM / 16, DIM, BATCH + 1), 128>>>(
        x, cw, cb, g, bta, Y, w1, w2, W1, W2);

    // 2) GEMM1 persistent + fast GELU -> H (bf16 tile-blocks)
    gemm1_persist<<<296, 128, SMEM_G1>>>(Y, W1, b1, H);

    // 3) GEMM2 + bias + transposed residual -> out (fp32)
    gemm2_bf16<<<dim3(2, M_ROWS / 128), 128, SMEM_G2>>>(H, W2, b2, x, out);
}